// round 9
// baseline (speedup 1.0000x reference)
#include <cuda_runtime.h>
#include <cuda_fp16.h>
#include <cstdint>
#include <math.h>

#define BATCH   1024
#define SEQ     96
#define INSZ    128
#define HID     1024
#define G4      4096
#define HORIZON 24
#define OUTSZ   128
#define KCAT    1152   // 128 + 1024  (x | h  — input part FIRST)

#define CK      64     // K elements per chunk (halves)
#define SMS_H   72     // smem row stride in halves (144B rows; ldmatrix conflict-free)
#define NCTA    128

#define AS_ST   (128 * SMS_H)
#define BS_ST   (256 * SMS_H)
#define SMEM_P  (3 * (AS_ST + BS_ST) * 2)   // 82,944 B

// ---------------------------------------------------------------------------
// Scratch (device globals; allocation is forbidden)
// ---------------------------------------------------------------------------
__device__ __align__(16) __half g_h   [2 * BATCH * HID];    // encoder h ping-pong (fp16)
__device__ __align__(16) float  g_c   [BATCH * HID];        // encoder c (fp32)
__device__ __align__(16) __half g_hcat[2 * BATCH * KCAT];   // decoder [out_prev | h] ping-pong
__device__ __align__(16) float  g_cd  [BATCH * HID];        // decoder c
__device__ __align__(16) __half g_xh  [BATCH * SEQ * INSZ]; // x converted to fp16
__device__ __align__(16) __half g_We  [G4 * KCAT];          // gate-interleaved [W_ih_e|W_hh_e]
__device__ __align__(16) __half g_Wd  [G4 * KCAT];
__device__ __align__(16) __half g_Wfc [HID * HID];
__device__ __align__(16) __half g_Wfcc[HID * HID];
__device__ __align__(16) __half g_Wout[OUTSZ * HID];
__device__ __align__(16) float  g_be  [G4];
__device__ __align__(16) float  g_bd  [G4];
__device__ unsigned g_bar_cnt = 0;
__device__ unsigned g_bar_phase = 0;

// ---------------------------------------------------------------------------
// Helpers
// ---------------------------------------------------------------------------
__device__ __forceinline__ void mma_f16(float* c, const uint32_t* a, const uint32_t* b) {
    asm volatile(
        "mma.sync.aligned.m16n8k16.row.col.f32.f16.f16.f32 "
        "{%0,%1,%2,%3}, {%4,%5,%6,%7}, {%8,%9}, {%0,%1,%2,%3};"
        : "+f"(c[0]), "+f"(c[1]), "+f"(c[2]), "+f"(c[3])
        : "r"(a[0]), "r"(a[1]), "r"(a[2]), "r"(a[3]), "r"(b[0]), "r"(b[1]));
}
__device__ __forceinline__ void ldsm4(uint32_t* r, uint32_t saddr) {
    asm volatile("ldmatrix.sync.aligned.m8n8.x4.shared.b16 {%0,%1,%2,%3}, [%4];"
        : "=r"(r[0]), "=r"(r[1]), "=r"(r[2]), "=r"(r[3]) : "r"(saddr));
}
__device__ __forceinline__ void cp16h(__half* smem, const __half* g) {
    uint32_t s = (uint32_t)__cvta_generic_to_shared(smem);
    asm volatile("cp.async.cg.shared.global [%0], [%1], 16;" :: "r"(s), "l"(g));
}
__device__ __forceinline__ uint32_t smem_u32(const void* p) {
    return (uint32_t)__cvta_generic_to_shared(p);
}
__device__ __forceinline__ float fsig(float x) {
    return __fdividef(1.0f, 1.0f + __expf(-x));
}
__device__ __forceinline__ float ftanh(float x) {
    return __fdividef(2.0f, 1.0f + __expf(-2.0f * x)) - 1.0f;
}

// sense-reversing grid barrier (all NCTA CTAs guaranteed co-resident)
__device__ __forceinline__ void grid_bar() {
    __syncthreads();
    if (threadIdx.x == 0) {
        __threadfence();
        unsigned my = *(volatile unsigned*)&g_bar_phase;
        unsigned old = atomicAdd(&g_bar_cnt, 1u);
        if (old == NCTA - 1) {
            g_bar_cnt = 0;
            __threadfence();
            atomicAdd(&g_bar_phase, 1u);
        } else {
            while (*(volatile unsigned*)&g_bar_phase == my) { __nanosleep(32); }
        }
    }
    __syncthreads();
}

// ---------------------------------------------------------------------------
// Prep kernels. New concat order: cols [0:128) = W_ih, [128:1152) = W_hh,
// rows gate-interleaved (row 4j+g <- orow g*1024+j).
// ---------------------------------------------------------------------------
__global__ void prep_w(const float* __restrict__ Whh, const float* __restrict__ Wih,
                       const float* __restrict__ b1, const float* __restrict__ b2,
                       __half* __restrict__ Wcat, float* __restrict__ bcat)
{
    long idx = (long)blockIdx.x * blockDim.x + threadIdx.x;
    if (idx >= (long)G4 * KCAT) return;
    int row = (int)(idx / KCAT);
    int k   = (int)(idx % KCAT);
    int j = row >> 2, g = row & 3;
    int orow = g * HID + j;
    float w = (k < INSZ) ? Wih[(size_t)orow * INSZ + k]
                         : Whh[(size_t)orow * HID + (k - INSZ)];
    Wcat[idx] = __float2half_rn(w);
    if (k == 0) bcat[row] = b1[orow] + b2[orow];
}

__global__ void f2h(const float* __restrict__ src, __half* __restrict__ dst, long n)
{
    long i = (long)blockIdx.x * blockDim.x + threadIdx.x;
    if (i < n) dst[i] = __float2half_rn(src[i]);
}

// ---------------------------------------------------------------------------
// Unified pipelined GEMM executor (device-side, called from persistent kernel)
// CTA tile 128 x bn (bn = 256 or 128), 16 warps (warp 32x64; wn>=bn/64 idle).
// K chunks [cb, ce): chunk < hsplit reads Ain at k0; else Ah at k0-hsplit*64.
// Pipeline: 3-stage ring carried across calls via sp. Exactly one commit_group
// per loop iteration; iterations past ce issue next-call chunks from pnA
// (prefetch) or commit empty groups. selfProlog: issue chunks cb, cb+1 first.
// MODE 0: LSTM epilogue (gate-interleaved cols; O1 = fp16 h, O2 = fp32 c).
// MODE 1: bias epilogue -> fp16 O1.   MODE 2: bias -> fp32 O1.
// MODE 3: bias -> fp32 O1 + fp16 O2 copy.
// ---------------------------------------------------------------------------
template<int MODE>
__device__ __forceinline__ int exec_gemm(
    int sp, int selfProlog,
    const __half* Ain, int ldai,
    const __half* Ah,  int ldah, int hsplit,
    const __half* B,   int ldb,  int bn,
    const float* bias,
    void* O1v, int ldo1, void* O2v, int ldo2,
    int cb, int ce, int first,
    const __half* pnA, int ldpn,
    int m0, int n0, __half* smh)
{
    __half* As = smh;
    __half* Bs = smh + 3 * AS_ST;

    const int tid  = threadIdx.x;
    const int lane = tid & 31;
    const int wid  = tid >> 5;
    const int wm   = wid & 3;      // wid % 4
    const int wn   = wid >> 2;     // wid / 4
    const int lr   = lane >> 2;
    const int lc   = lane & 3;
    const int act  = (wn * 64 < bn);
    const int ib   = bn >> 6;      // B 16B-granules per thread per chunk

    const int a_row  = lane & 15;
    const int a_koff = (lane >> 4) << 3;
    const int b_row  = ((lane >> 4) << 3) + (lane & 7);
    const int b_koff = ((lane >> 3) & 1) << 3;

    float acc[2][8][4];
    #pragma unroll
    for (int mi = 0; mi < 2; mi++)
        #pragma unroll
        for (int nf = 0; nf < 8; nf++)
            #pragma unroll
            for (int t = 0; t < 4; t++) acc[mi][nf][t] = 0.0f;

    auto load_chunk = [&](int st, int idx) {
        const __half* Asrc = nullptr; int lda = 0, koff = 0, k0 = 0;
        if (idx < ce) {
            k0 = idx * CK;
            if (idx < hsplit) { Asrc = Ain; lda = ldai; koff = k0; }
            else              { Asrc = Ah;  lda = ldah; koff = k0 - hsplit * CK; }
        } else if (pnA) {
            int v = idx - ce;          // 0 or 1: next call's input-part chunks
            k0 = v * CK;
            Asrc = pnA; lda = ldpn; koff = k0;
        }
        if (Asrc) {
            __half* as = As + st * AS_ST;
            __half* bs = Bs + st * BS_ST;
            #pragma unroll
            for (int i = 0; i < 2; i++) {
                int q = tid + i * 512;
                int r = q >> 3, c8 = (q & 7) * 8;
                cp16h(as + r * SMS_H + c8, Asrc + (size_t)(m0 + r) * lda + koff + c8);
            }
            for (int i = 0; i < ib; i++) {
                int q = tid + i * 512;
                int r = q >> 3, c8 = (q & 7) * 8;
                cp16h(bs + r * SMS_H + c8, B + (size_t)(n0 + r) * ldb + k0 + c8);
            }
        }
        asm volatile("cp.async.commit_group;");
    };

    if (selfProlog) {
        load_chunk(sp % 3, cb);
        load_chunk((sp + 1) % 3, cb + 1);
    }

    const int nch = ce - cb;
    #pragma unroll 1
    for (int it = 0; it < nch; it++) {
        asm volatile("cp.async.wait_group 1;");
        __syncthreads();
        load_chunk((sp + it + 2) % 3, cb + it + 2);

        if (act) {
            const int st = (sp + it) % 3;
            const uint32_t as_u = smem_u32(As + st * AS_ST + (wm * 32) * SMS_H);
            const uint32_t bs_u = smem_u32(Bs + st * BS_ST + (wn * 64) * SMS_H);
            #pragma unroll
            for (int ks = 0; ks < 4; ks++) {
                const int kk = ks * 16;
                uint32_t af[2][4];
                #pragma unroll
                for (int mi = 0; mi < 2; mi++)
                    ldsm4(af[mi], as_u + (uint32_t)(((mi * 16 + a_row) * SMS_H + kk + a_koff) * 2));
                #pragma unroll
                for (int nfp = 0; nfp < 4; nfp++) {
                    uint32_t bf4[4];
                    ldsm4(bf4, bs_u + (uint32_t)(((nfp * 16 + b_row) * SMS_H + kk + b_koff) * 2));
                    #pragma unroll
                    for (int mi = 0; mi < 2; mi++) {
                        mma_f16(acc[mi][nfp * 2],     af[mi], &bf4[0]);
                        mma_f16(acc[mi][nfp * 2 + 1], af[mi], &bf4[2]);
                    }
                }
            }
        }
    }

    if (act) {
        const int rb = m0 + wm * 32 + lr;
        if (MODE == 0) {
            __half* O1 = (__half*)O1v;
            float*  O2 = (float*)O2v;
            #pragma unroll
            for (int mi = 0; mi < 2; mi++) {
                #pragma unroll
                for (int nf = 0; nf < 8; nf++) {
                    int cg = n0 + wn * 64 + nf * 8 + 2 * lc;   // = 4j+g (even)
                    float v0 = acc[mi][nf][0] + bias[cg];
                    float v1 = acc[mi][nf][1] + bias[cg + 1];
                    float v2 = acc[mi][nf][2] + bias[cg];
                    float v3 = acc[mi][nf][3] + bias[cg + 1];
                    float p0 = __shfl_xor_sync(0xffffffffu, v0, 1);
                    float p1 = __shfl_xor_sync(0xffffffffu, v1, 1);
                    float p2 = __shfl_xor_sync(0xffffffffu, v2, 1);
                    float p3 = __shfl_xor_sync(0xffffffffu, v3, 1);
                    if ((lane & 1) == 0) {
                        int j  = cg >> 2;
                        int r0 = rb + mi * 16, r1 = r0 + 8;
                        {
                            float i_ = fsig(v0), f_ = fsig(v1);
                            float g_ = ftanh(p0), o_ = fsig(p1);
                            float co = first ? 0.0f : O2[(size_t)r0 * ldo2 + j];
                            float cn = f_ * co + i_ * g_;
                            O2[(size_t)r0 * ldo2 + j] = cn;
                            O1[(size_t)r0 * ldo1 + j] = __float2half_rn(o_ * ftanh(cn));
                        }
                        {
                            float i_ = fsig(v2), f_ = fsig(v3);
                            float g_ = ftanh(p2), o_ = fsig(p3);
                            float co = first ? 0.0f : O2[(size_t)r1 * ldo2 + j];
                            float cn = f_ * co + i_ * g_;
                            O2[(size_t)r1 * ldo2 + j] = cn;
                            O1[(size_t)r1 * ldo1 + j] = __float2half_rn(o_ * ftanh(cn));
                        }
                    }
                }
            }
        } else {
            #pragma unroll
            for (int mi = 0; mi < 2; mi++) {
                #pragma unroll
                for (int nf = 0; nf < 8; nf++) {
                    int cg = n0 + wn * 64 + nf * 8 + 2 * lc;
                    float b0 = bias[cg], b1 = bias[cg + 1];
                    int r0 = rb + mi * 16, r1 = r0 + 8;
                    float u0 = acc[mi][nf][0] + b0, u1 = acc[mi][nf][1] + b1;
                    float u2 = acc[mi][nf][2] + b0, u3 = acc[mi][nf][3] + b1;
                    if (MODE == 1) {
                        __half* O1 = (__half*)O1v;
                        *(__half2*)&O1[(size_t)r0 * ldo1 + cg] = __floats2half2_rn(u0, u1);
                        *(__half2*)&O1[(size_t)r1 * ldo1 + cg] = __floats2half2_rn(u2, u3);
                    } else {
                        float* O1 = (float*)O1v;
                        *(float2*)&O1[(size_t)r0 * ldo1 + cg] = make_float2(u0, u1);
                        *(float2*)&O1[(size_t)r1 * ldo1 + cg] = make_float2(u2, u3);
                        if (MODE == 3) {
                            __half* O2 = (__half*)O2v;
                            *(__half2*)&O2[(size_t)r0 * ldo2 + cg] = __floats2half2_rn(u0, u1);
                            *(__half2*)&O2[(size_t)r1 * ldo2 + cg] = __floats2half2_rn(u2, u3);
                        }
                    }
                }
            }
        }
    }
    return (sp + nch) % 3;
}

// ---------------------------------------------------------------------------
// Persistent kernel: encoder 96 steps + bridge + decoder 24x(step + out-proj)
// grid (16, 8) = 128 CTAs, 512 threads, 82.9KB smem -> 1 CTA/SM, all resident.
// ---------------------------------------------------------------------------
__global__ void __launch_bounds__(512, 1)
lstm_persist(const __half* __restrict__ xh,
             const __half* __restrict__ We, const float* __restrict__ be,
             const __half* __restrict__ Wd, const float* __restrict__ bd,
             const __half* __restrict__ Wfc,  const float* __restrict__ b_fc,
             const __half* __restrict__ Wfcc, const float* __restrict__ b_fcc,
             const __half* __restrict__ Wout, const float* __restrict__ b_out,
             __half* __restrict__ h, float* __restrict__ c,
             __half* __restrict__ hcat, float* __restrict__ cd,
             float* __restrict__ out)
{
    extern __shared__ __half smh[];
    const int bx = blockIdx.x;
    const int by = blockIdx.y;
    const int m0 = by * 128;
    int sp = 0;

    // ---- encoder: 96 steps ----
    int p = 0;
    for (int t = 0; t < SEQ; t++) {
        const __half* pn = (t < SEQ - 1) ? (xh + (size_t)(t + 1) * INSZ) : nullptr;
        sp = exec_gemm<0>(sp, (t == 0) ? 1 : 0,
            xh + (size_t)t * INSZ, SEQ * INSZ,
            h + (size_t)p * BATCH * HID, HID, 2,
            We, KCAT, 256, be,
            h + (size_t)(1 - p) * BATCH * HID, HID, c, HID,
            0, (t == 0) ? 2 : 18, (t == 0) ? 1 : 0,
            pn, SEQ * INSZ,
            m0, bx * 256, smh);
        p ^= 1;
        __threadfence();
        grid_bar();
    }
    const __half* hfin = h + (size_t)p * BATCH * HID;

    // ---- bridge (parallel: 64 CTAs Wfc -> h_dec fp16, 64 CTAs Wfcc -> cd) ----
    __half* hc0 = hcat;
    __half* hc1 = hcat + (size_t)BATCH * KCAT;
    if (bx < 8) {
        sp = exec_gemm<1>(sp, 1,
            nullptr, 0, hfin, HID, 0,
            Wfc, HID, 128, b_fc,
            hc0 + INSZ, KCAT, nullptr, 0,
            0, 16, 0, nullptr, 0,
            m0, bx * 128, smh);
    } else {
        sp = exec_gemm<2>(sp, 1,
            nullptr, 0, hfin, HID, 0,
            Wfcc, HID, 128, b_fcc,
            cd, HID, nullptr, 0,
            0, 16, 0, nullptr, 0,
            m0, (bx - 8) * 128, smh);
    }
    __threadfence();
    grid_bar();

    // ---- decoder: 24 x (fused step; out-proj on 8 CTAs) ----
    int q = 0;
    for (int t = 0; t < HORIZON; t++) {
        __half* src = q ? hc1 : hc0;
        __half* dst = q ? hc0 : hc1;
        sp = exec_gemm<0>(sp, 1,
            src, KCAT,                 // out_prev part (cols 0..127)
            src + INSZ, KCAT, 2,       // h part
            Wd, KCAT, 256, bd,
            dst + INSZ, KCAT, cd, HID,
            (t == 0) ? 2 : 0, 18, 0,
            nullptr, 0,
            m0, bx * 256, smh);
        __threadfence();
        grid_bar();
        if (bx == 0) {
            sp = exec_gemm<3>(sp, 1,
                nullptr, 0, dst + INSZ, KCAT, 0,
                Wout, HID, 128, b_out,
                out + (size_t)t * OUTSZ, HORIZON * OUTSZ,
                dst, KCAT,
                0, 16, 0, nullptr, 0,
                m0, 0, smh);
        }
        __threadfence();
        grid_bar();
        q ^= 1;
    }
}

// ---------------------------------------------------------------------------
// Launch sequence (graph-capturable: kernel launches only)
// ---------------------------------------------------------------------------
extern "C" void kernel_launch(void* const* d_in, const int* in_sizes, int n_in,
                              void* d_out, int out_size)
{
    const float* x      = (const float*)d_in[0];
    const float* W_ih_e = (const float*)d_in[1];
    const float* W_hh_e = (const float*)d_in[2];
    const float* b_ih_e = (const float*)d_in[3];
    const float* b_hh_e = (const float*)d_in[4];
    const float* W_ih_d = (const float*)d_in[5];
    const float* W_hh_d = (const float*)d_in[6];
    const float* b_ih_d = (const float*)d_in[7];
    const float* b_hh_d = (const float*)d_in[8];
    const float* W_fc   = (const float*)d_in[9];
    const float* b_fc   = (const float*)d_in[10];
    const float* W_fcc  = (const float*)d_in[11];
    const float* b_fcc  = (const float*)d_in[12];
    const float* W_out  = (const float*)d_in[13];
    const float* b_out  = (const float*)d_in[14];
    float* out = (float*)d_out;

    __half *h, *hcat, *xh, *We, *Wd, *Wfc, *Wfcc, *Wout;
    float *c, *cd, *be, *bd;
    cudaGetSymbolAddress((void**)&h,    g_h);
    cudaGetSymbolAddress((void**)&c,    g_c);
    cudaGetSymbolAddress((void**)&hcat, g_hcat);
    cudaGetSymbolAddress((void**)&cd,   g_cd);
    cudaGetSymbolAddress((void**)&xh,   g_xh);
    cudaGetSymbolAddress((void**)&We,   g_We);
    cudaGetSymbolAddress((void**)&Wd,   g_Wd);
    cudaGetSymbolAddress((void**)&Wfc,  g_Wfc);
    cudaGetSymbolAddress((void**)&Wfcc, g_Wfcc);
    cudaGetSymbolAddress((void**)&Wout, g_Wout);
    cudaGetSymbolAddress((void**)&be,   g_be);
    cudaGetSymbolAddress((void**)&bd,   g_bd);

    cudaFuncSetAttribute(lstm_persist, cudaFuncAttributeMaxDynamicSharedMemorySize, SMEM_P);

    // ---- prep: weights + x to fp16 ----
    {
        long total = (long)G4 * KCAT;
        int blocks = (int)((total + 255) / 256);
        prep_w<<<blocks, 256>>>(W_hh_e, W_ih_e, b_ih_e, b_hh_e, We, be);
        prep_w<<<blocks, 256>>>(W_hh_d, W_ih_d, b_ih_d, b_hh_d, Wd, bd);
        long nx = (long)BATCH * SEQ * INSZ;
        f2h<<<(int)((nx + 255) / 256), 256>>>(x, xh, nx);
        long nw = (long)HID * HID;
        f2h<<<(int)((nw + 255) / 256), 256>>>(W_fc,  Wfc,  nw);
        f2h<<<(int)((nw + 255) / 256), 256>>>(W_fcc, Wfcc, nw);
        long no = (long)OUTSZ * HID;
        f2h<<<(int)((no + 255) / 256), 256>>>(W_out, Wout, no);
    }

    // ---- one persistent kernel for everything ----
    lstm_persist<<<dim3(16, 8), 512, SMEM_P>>>(
        xh, We, be, Wd, bd, Wfc, b_fc, Wfcc, b_fcc, Wout, b_out,
        h, c, hcat, cd, out);
}

// round 10
// speedup vs baseline: 1.1284x; 1.1284x over previous
#include <cuda_runtime.h>
#include <cuda_fp16.h>
#include <cstdint>
#include <math.h>

#define BATCH   1024
#define SEQ     96
#define INSZ    128
#define HID     1024
#define G4      4096
#define HORIZON 24
#define OUTSZ   128
#define KCAT    1152   // 1024 + 128 (h | x)

#define CK      64     // K elements per chunk (halves)
#define HCH     16     // chunks from A1 (h part)
#define SMS_H   72     // smem row stride in halves (144B rows; ldmatrix conflict-free)
#define STAGES  4

// ---------------------------------------------------------------------------
// Scratch (device globals; allocation is forbidden)
// ---------------------------------------------------------------------------
__device__ __align__(16) __half g_h   [2 * BATCH * HID];     // encoder h ping-pong
__device__ __align__(16) float  g_c   [BATCH * HID];         // encoder c (fp32)
__device__ __align__(16) __half g_hall[(HORIZON + 1) * BATCH * HID]; // slot0=h_dec, slot t+1=h_t
__device__ __align__(16) float  g_cd  [BATCH * HID];         // decoder c
__device__ __align__(16) __half g_xh  [BATCH * SEQ * INSZ];  // x in fp16
__device__ __align__(16) __half g_We  [G4 * KCAT];           // gate-interleaved [W_hh_e|W_ih_e]
__device__ __align__(16) __half g_Wd0 [G4 * HID];            // plain W_hh_d (gate-interleaved)
__device__ __align__(16) __half g_Wdf [G4 * HID];            // folded W_hh_d + W_ih_d@W_out
__device__ __align__(16) __half g_Wfc [HID * HID];
__device__ __align__(16) __half g_Wfcc[HID * HID];
__device__ __align__(16) __half g_Wout[OUTSZ * HID];
__device__ __align__(16) float  g_be  [G4];
__device__ __align__(16) float  g_bd0 [G4];
__device__ __align__(16) float  g_bdf [G4];

// ---------------------------------------------------------------------------
// Helpers
// ---------------------------------------------------------------------------
__device__ __forceinline__ void mma_f16(float* c, const uint32_t* a, const uint32_t* b) {
    asm volatile(
        "mma.sync.aligned.m16n8k16.row.col.f32.f16.f16.f32 "
        "{%0,%1,%2,%3}, {%4,%5,%6,%7}, {%8,%9}, {%0,%1,%2,%3};"
        : "+f"(c[0]), "+f"(c[1]), "+f"(c[2]), "+f"(c[3])
        : "r"(a[0]), "r"(a[1]), "r"(a[2]), "r"(a[3]), "r"(b[0]), "r"(b[1]));
}
__device__ __forceinline__ void ldsm4(uint32_t* r, uint32_t saddr) {
    asm volatile("ldmatrix.sync.aligned.m8n8.x4.shared.b16 {%0,%1,%2,%3}, [%4];"
        : "=r"(r[0]), "=r"(r[1]), "=r"(r[2]), "=r"(r[3]) : "r"(saddr));
}
__device__ __forceinline__ void cp16h(__half* smem, const __half* g) {
    uint32_t s = (uint32_t)__cvta_generic_to_shared(smem);
    asm volatile("cp.async.cg.shared.global [%0], [%1], 16;" :: "r"(s), "l"(g));
}
__device__ __forceinline__ uint32_t smem_u32(const void* p) {
    return (uint32_t)__cvta_generic_to_shared(p);
}
__device__ __forceinline__ float fsig(float x) {
    return __fdividef(1.0f, 1.0f + __expf(-x));
}
__device__ __forceinline__ float ftanh(float x) {
    return __fdividef(2.0f, 1.0f + __expf(-2.0f * x)) - 1.0f;
}

// ---------------------------------------------------------------------------
// Prep kernels
// ---------------------------------------------------------------------------
__global__ void prep_w(const float* __restrict__ Whh, const float* __restrict__ Wih,
                       const float* __restrict__ b1, const float* __restrict__ b2,
                       __half* __restrict__ Wcat, float* __restrict__ bcat)
{
    long idx = (long)blockIdx.x * blockDim.x + threadIdx.x;
    if (idx >= (long)G4 * KCAT) return;
    int row = (int)(idx / KCAT);
    int k   = (int)(idx % KCAT);
    int j = row >> 2, g = row & 3;
    int orow = g * HID + j;
    float w = (k < HID) ? Whh[(size_t)orow * HID + k]
                        : Wih[(size_t)orow * INSZ + (k - HID)];
    Wcat[idx] = __float2half_rn(w);
    if (k == 0) bcat[row] = b1[orow] + b2[orow];
}

// Decoder fold: Wd0 = Whh (interleaved), Wdf = Whh + Wih@Wout (interleaved),
// bd0 = b_ih+b_hh, bdf = bd0 + Wih@b_out. 16 rows per block.
__global__ void __launch_bounds__(256)
prep_wd(const float* __restrict__ Whh, const float* __restrict__ Wih,
        const float* __restrict__ Wout,
        const float* __restrict__ b1, const float* __restrict__ b2,
        const float* __restrict__ bo,
        __half* __restrict__ Wd0, __half* __restrict__ Wdf,
        float* __restrict__ bd0, float* __restrict__ bdf)
{
    __shared__ float wih_s[16][INSZ];
    __shared__ int orow_s[16];
    const int tid = threadIdx.x;
    const int rb = blockIdx.x * 16;
    if (tid < 16) {
        int row = rb + tid;
        orow_s[tid] = (row & 3) * HID + (row >> 2);
    }
    __syncthreads();
    for (int i = tid; i < 16 * INSZ; i += 256) {
        int r = i >> 7, o = i & 127;
        wih_s[r][o] = Wih[(size_t)orow_s[r] * INSZ + o];
    }
    __syncthreads();
    if (tid < 16) {
        float bf = 0.0f;
        for (int o = 0; o < INSZ; o++) bf += wih_s[tid][o] * bo[o];
        int orow = orow_s[tid];
        float bb = b1[orow] + b2[orow];
        bd0[rb + tid] = bb;
        bdf[rb + tid] = bb + bf;
    }
    for (int nc = 0; nc < 4; nc++) {
        int n = nc * 256 + tid;
        float acc[16], w0[16];
        #pragma unroll
        for (int r = 0; r < 16; r++) {
            w0[r] = Whh[(size_t)orow_s[r] * HID + n];
            acc[r] = w0[r];
        }
        for (int o = 0; o < INSZ; o++) {
            float w = Wout[(size_t)o * HID + n];
            #pragma unroll
            for (int r = 0; r < 16; r++) acc[r] += wih_s[r][o] * w;
        }
        #pragma unroll
        for (int r = 0; r < 16; r++) {
            Wd0[(size_t)(rb + r) * HID + n] = __float2half_rn(w0[r]);
            Wdf[(size_t)(rb + r) * HID + n] = __float2half_rn(acc[r]);
        }
    }
}

__global__ void f2h(const float* __restrict__ src, __half* __restrict__ dst, long n)
{
    long i = (long)blockIdx.x * blockDim.x + threadIdx.x;
    if (i < n) dst[i] = __float2half_rn(src[i]);
}

// ---------------------------------------------------------------------------
// Core GEMM (fp16 operands, fp32 accum), 4-stage cp.async pipeline, one
// __syncthreads per K-chunk, ldmatrix fragment loads. Warp tile 32x64.
// K chunks [cb, ce): chunk < HCH reads A1 (lda1); else A2 at k-1024 (lda2).
// MODE 0: LSTM epilogue (gate-interleaved cols; fp16 h -> O1, fp32 c -> O2)
// MODE 1: bias -> fp16 O1.  MODE 2: bias -> fp32 O1.
// MODE 4: bias -> fp32 scatter: row r -> out[(r&1023)*T*O + (r>>10)*O + col].
// ---------------------------------------------------------------------------
template<int TBM, int BN, int MODE>
__global__ void __launch_bounds__((TBM / 32) * (BN / 64) * 32)
gemm_h(const __half* __restrict__ A1, int lda1,
       const __half* __restrict__ A2, int lda2,
       const __half* __restrict__ B,  int ldb,
       const float* __restrict__ bias,
       void* __restrict__ O1v, int ldo1,
       void* __restrict__ O2v, int ldo2,
       int cb, int ce, int first)
{
    constexpr int WM = TBM / 32;
    constexpr int WN = BN / 64;
    constexpr int NT = WM * WN * 32;
    constexpr int AS_ST = TBM * SMS_H;
    constexpr int BS_ST = BN * SMS_H;
    constexpr int IA = TBM * 8 / NT;
    constexpr int IB = BN * 8 / NT;

    extern __shared__ __half smh[];
    __half* As = smh;
    __half* Bs = smh + STAGES * AS_ST;

    const int tid  = threadIdx.x;
    const int lane = tid & 31;
    const int wid  = tid >> 5;
    const int wm   = wid % WM;
    const int wn   = wid / WM;
    const int lr   = lane >> 2;
    const int lc   = lane & 3;
    const int m0   = blockIdx.y * TBM;
    const int n0   = blockIdx.x * BN;

    const int a_row  = lane & 15;
    const int a_koff = (lane >> 4) << 3;
    const int b_row  = ((lane >> 4) << 3) + (lane & 7);
    const int b_koff = ((lane >> 3) & 1) << 3;

    float acc[2][8][4];
    #pragma unroll
    for (int mi = 0; mi < 2; mi++)
        #pragma unroll
        for (int nf = 0; nf < 8; nf++)
            #pragma unroll
            for (int t = 0; t < 4; t++) acc[mi][nf][t] = 0.0f;

    auto load_chunk = [&](int st, int chunk) {
        if (chunk < ce) {
            __half* as = As + st * AS_ST;
            __half* bs = Bs + st * BS_ST;
            const int k0 = chunk * CK;
            #pragma unroll
            for (int i = 0; i < IA; i++) {
                int q = tid + i * NT;
                int r = q >> 3, c8 = (q & 7) * 8;
                const __half* src = (chunk < HCH)
                    ? A1 + (size_t)(m0 + r) * lda1 + k0 + c8
                    : A2 + (size_t)(m0 + r) * lda2 + (k0 - HID) + c8;
                cp16h(as + r * SMS_H + c8, src);
            }
            #pragma unroll
            for (int i = 0; i < IB; i++) {
                int q = tid + i * NT;
                int r = q >> 3, c8 = (q & 7) * 8;
                cp16h(bs + r * SMS_H + c8, B + (size_t)(n0 + r) * ldb + k0 + c8);
            }
        }
        asm volatile("cp.async.commit_group;");
    };

    load_chunk(0, cb);
    load_chunk(1, cb + 1);
    load_chunk(2, cb + 2);

    for (int ch = cb; ch < ce; ch++) {
        const int it = ch - cb;
        asm volatile("cp.async.wait_group 2;");
        __syncthreads();
        // Stage (it+3)%4 == (it-1)%4, consumed before the sync above.
        load_chunk((it + 3) & 3, ch + 3);

        const int st = it & 3;
        const uint32_t as_u = smem_u32(As + st * AS_ST + (wm * 32) * SMS_H);
        const uint32_t bs_u = smem_u32(Bs + st * BS_ST + (wn * 64) * SMS_H);
        #pragma unroll
        for (int ks = 0; ks < 4; ks++) {
            const int kk = ks * 16;
            uint32_t af[2][4];
            #pragma unroll
            for (int mi = 0; mi < 2; mi++)
                ldsm4(af[mi], as_u + (uint32_t)(((mi * 16 + a_row) * SMS_H + kk + a_koff) * 2));
            #pragma unroll
            for (int nfp = 0; nfp < 4; nfp++) {
                uint32_t bf4[4];
                ldsm4(bf4, bs_u + (uint32_t)(((nfp * 16 + b_row) * SMS_H + kk + b_koff) * 2));
                #pragma unroll
                for (int mi = 0; mi < 2; mi++) {
                    mma_f16(acc[mi][nfp * 2],     af[mi], &bf4[0]);
                    mma_f16(acc[mi][nfp * 2 + 1], af[mi], &bf4[2]);
                }
            }
        }
    }

    const int rb = m0 + wm * 32 + lr;
    if (MODE == 0) {
        __half* O1 = (__half*)O1v;
        float*  O2 = (float*)O2v;
        #pragma unroll
        for (int mi = 0; mi < 2; mi++) {
            #pragma unroll
            for (int nf = 0; nf < 8; nf++) {
                int cg = n0 + wn * 64 + nf * 8 + 2 * lc;   // = 4j+g (even)
                float v0 = acc[mi][nf][0] + bias[cg];
                float v1 = acc[mi][nf][1] + bias[cg + 1];
                float v2 = acc[mi][nf][2] + bias[cg];
                float v3 = acc[mi][nf][3] + bias[cg + 1];
                float p0 = __shfl_xor_sync(0xffffffffu, v0, 1);
                float p1 = __shfl_xor_sync(0xffffffffu, v1, 1);
                float p2 = __shfl_xor_sync(0xffffffffu, v2, 1);
                float p3 = __shfl_xor_sync(0xffffffffu, v3, 1);
                if ((lane & 1) == 0) {
                    int j  = cg >> 2;
                    int r0 = rb + mi * 16, r1 = r0 + 8;
                    {
                        float i_ = fsig(v0), f_ = fsig(v1);
                        float g_ = ftanh(p0), o_ = fsig(p1);
                        float co = first ? 0.0f : O2[(size_t)r0 * ldo2 + j];
                        float cn = f_ * co + i_ * g_;
                        O2[(size_t)r0 * ldo2 + j] = cn;
                        O1[(size_t)r0 * ldo1 + j] = __float2half_rn(o_ * ftanh(cn));
                    }
                    {
                        float i_ = fsig(v2), f_ = fsig(v3);
                        float g_ = ftanh(p2), o_ = fsig(p3);
                        float co = first ? 0.0f : O2[(size_t)r1 * ldo2 + j];
                        float cn = f_ * co + i_ * g_;
                        O2[(size_t)r1 * ldo2 + j] = cn;
                        O1[(size_t)r1 * ldo1 + j] = __float2half_rn(o_ * ftanh(cn));
                    }
                }
            }
        }
    } else {
        #pragma unroll
        for (int mi = 0; mi < 2; mi++) {
            #pragma unroll
            for (int nf = 0; nf < 8; nf++) {
                int cg = n0 + wn * 64 + nf * 8 + 2 * lc;
                float b0 = bias[cg], b1 = bias[cg + 1];
                int r0 = rb + mi * 16, r1 = r0 + 8;
                float u0 = acc[mi][nf][0] + b0, u1 = acc[mi][nf][1] + b1;
                float u2 = acc[mi][nf][2] + b0, u3 = acc[mi][nf][3] + b1;
                if (MODE == 1) {
                    __half* O1 = (__half*)O1v;
                    *(__half2*)&O1[(size_t)r0 * ldo1 + cg] = __floats2half2_rn(u0, u1);
                    *(__half2*)&O1[(size_t)r1 * ldo1 + cg] = __floats2half2_rn(u2, u3);
                } else if (MODE == 2) {
                    float* O1 = (float*)O1v;
                    *(float2*)&O1[(size_t)r0 * ldo1 + cg] = make_float2(u0, u1);
                    *(float2*)&O1[(size_t)r1 * ldo1 + cg] = make_float2(u2, u3);
                } else {   // MODE 4: scatter
                    float* O1 = (float*)O1v;
                    size_t i0 = (size_t)(r0 & 1023) * (HORIZON * OUTSZ) + (size_t)(r0 >> 10) * OUTSZ + cg;
                    size_t i1 = (size_t)(r1 & 1023) * (HORIZON * OUTSZ) + (size_t)(r1 >> 10) * OUTSZ + cg;
                    *(float2*)&O1[i0] = make_float2(u0, u1);
                    *(float2*)&O1[i1] = make_float2(u2, u3);
                }
            }
        }
    }
}

// ---------------------------------------------------------------------------
// Launch sequence (graph-capturable: kernel launches only)
// ---------------------------------------------------------------------------
extern "C" void kernel_launch(void* const* d_in, const int* in_sizes, int n_in,
                              void* d_out, int out_size)
{
    const float* x      = (const float*)d_in[0];
    const float* W_ih_e = (const float*)d_in[1];
    const float* W_hh_e = (const float*)d_in[2];
    const float* b_ih_e = (const float*)d_in[3];
    const float* b_hh_e = (const float*)d_in[4];
    const float* W_ih_d = (const float*)d_in[5];
    const float* W_hh_d = (const float*)d_in[6];
    const float* b_ih_d = (const float*)d_in[7];
    const float* b_hh_d = (const float*)d_in[8];
    const float* W_fc   = (const float*)d_in[9];
    const float* b_fc   = (const float*)d_in[10];
    const float* W_fcc  = (const float*)d_in[11];
    const float* b_fcc  = (const float*)d_in[12];
    const float* W_out  = (const float*)d_in[13];
    const float* b_out  = (const float*)d_in[14];
    float* out = (float*)d_out;

    __half *h, *hall, *xh, *We, *Wd0, *Wdf, *Wfc, *Wfcc, *Wout;
    float *c, *cd, *be, *bd0, *bdf;
    cudaGetSymbolAddress((void**)&h,    g_h);
    cudaGetSymbolAddress((void**)&c,    g_c);
    cudaGetSymbolAddress((void**)&hall, g_hall);
    cudaGetSymbolAddress((void**)&cd,   g_cd);
    cudaGetSymbolAddress((void**)&xh,   g_xh);
    cudaGetSymbolAddress((void**)&We,   g_We);
    cudaGetSymbolAddress((void**)&Wd0,  g_Wd0);
    cudaGetSymbolAddress((void**)&Wdf,  g_Wdf);
    cudaGetSymbolAddress((void**)&Wfc,  g_Wfc);
    cudaGetSymbolAddress((void**)&Wfcc, g_Wfcc);
    cudaGetSymbolAddress((void**)&Wout, g_Wout);
    cudaGetSymbolAddress((void**)&be,   g_be);
    cudaGetSymbolAddress((void**)&bd0,  g_bd0);
    cudaGetSymbolAddress((void**)&bdf,  g_bdf);

    const int SMEM_L = STAGES * (128 + 256) * SMS_H * 2;  // 221,184 B
    const int SMEM_B = STAGES * (128 + 128) * SMS_H * 2;  // 147,456 B
    cudaFuncSetAttribute((const void*)gemm_h<128, 256, 0>,
                         cudaFuncAttributeMaxDynamicSharedMemorySize, SMEM_L);
    cudaFuncSetAttribute((const void*)gemm_h<128, 128, 1>,
                         cudaFuncAttributeMaxDynamicSharedMemorySize, SMEM_B);
    cudaFuncSetAttribute((const void*)gemm_h<128, 128, 2>,
                         cudaFuncAttributeMaxDynamicSharedMemorySize, SMEM_B);
    cudaFuncSetAttribute((const void*)gemm_h<128, 128, 4>,
                         cudaFuncAttributeMaxDynamicSharedMemorySize, SMEM_B);

    // ---- prep ----
    {
        long total = (long)G4 * KCAT;
        int blocks = (int)((total + 255) / 256);
        prep_w<<<blocks, 256>>>(W_hh_e, W_ih_e, b_ih_e, b_hh_e, We, be);
        prep_wd<<<G4 / 16, 256>>>(W_hh_d, W_ih_d, W_out, b_ih_d, b_hh_d, b_out,
                                  Wd0, Wdf, bd0, bdf);
        long nx = (long)BATCH * SEQ * INSZ;
        f2h<<<(int)((nx + 255) / 256), 256>>>(x, xh, nx);
        long nw = (long)HID * HID;
        f2h<<<(int)((nw + 255) / 256), 256>>>(W_fc,  Wfc,  nw);
        f2h<<<(int)((nw + 255) / 256), 256>>>(W_fcc, Wfcc, nw);
        long no = (long)OUTSZ * HID;
        f2h<<<(int)((no + 255) / 256), 256>>>(W_out, Wout, no);
    }

    const size_t BH = (size_t)BATCH * HID;
    const dim3 gL(G4 / 256, BATCH / 128);       // (16, 8)
    const dim3 gB(HID / 128, BATCH / 128);      // (8, 8)
    const dim3 gF(1, (BATCH * HORIZON) / 128);  // (1, 192)

    // ---- encoder: 96 fused GEMM+LSTM steps ----
    int p = 0;
    for (int t = 0; t < SEQ; t++) {
        gemm_h<128, 256, 0><<<gL, 512, SMEM_L>>>(
            h + (size_t)p * BH, HID,
            xh + (size_t)t * INSZ, SEQ * INSZ,
            We, KCAT, be,
            h + (size_t)(1 - p) * BH, HID,
            c, HID,
            (t == 0) ? HCH : 0, 18, (t == 0) ? 1 : 0);
        p ^= 1;
    }
    __half* h_fin = h + (size_t)p * BH;

    // ---- bridge: h_dec (fp16) -> hall slot 0; c_dec (fp32) -> cd ----
    gemm_h<128, 128, 1><<<gB, 256, SMEM_B>>>(
        h_fin, HID, (const __half*)nullptr, 0, Wfc, HID, b_fc,
        hall, HID, nullptr, 0, 0, HCH, 0);
    gemm_h<128, 128, 2><<<gB, 256, SMEM_B>>>(
        h_fin, HID, (const __half*)nullptr, 0, Wfcc, HID, b_fcc,
        cd, HID, nullptr, 0, 0, HCH, 0);

    // ---- decoder: 24 folded steps (out-proj folded into weights; K=1024) ----
    for (int t = 0; t < HORIZON; t++) {
        gemm_h<128, 256, 0><<<gL, 512, SMEM_L>>>(
            hall + (size_t)t * BH, HID,
            (const __half*)nullptr, 0,
            (t == 0) ? Wd0 : Wdf, HID,
            (t == 0) ? bd0 : bdf,
            hall + (size_t)(t + 1) * BH, HID,
            cd, HID,
            0, HCH, 0);
    }

    // ---- batched output projection: out[b,t,:] = h_t[b] @ Wout^T + b_out ----
    gemm_h<128, 128, 4><<<gF, 256, SMEM_B>>>(
        hall + BH, HID, (const __half*)nullptr, 0, Wout, HID, b_out,
        out, 0, nullptr, 0, 0, HCH, 0);
}

// round 11
// speedup vs baseline: 1.1376x; 1.0082x over previous
#include <cuda_runtime.h>
#include <cuda_fp16.h>
#include <cstdint>
#include <math.h>

#define BATCH   1024
#define SEQ     96
#define INSZ    128
#define HID     1024
#define G4      4096
#define HORIZON 24
#define OUTSZ   128
#define KCAT    1152   // 1024 + 128 (h | x)

#define CK      64     // K elements per chunk (halves)
#define HCH     16     // chunks from A1 (h part)
#define SMS_H   72     // smem row stride in halves (144B rows; ldmatrix conflict-free)

// ---------------------------------------------------------------------------
// Scratch (device globals; allocation is forbidden)
// ---------------------------------------------------------------------------
__device__ __align__(16) __half g_h   [2 * BATCH * HID];     // encoder h ping-pong
__device__ __align__(16) float  g_c   [BATCH * HID];         // encoder c (fp32)
__device__ __align__(16) __half g_hall[(HORIZON + 1) * BATCH * HID]; // slot0=h_dec, slot t+1=h_t
__device__ __align__(16) float  g_cd  [BATCH * HID];         // decoder c
__device__ __align__(16) __half g_xh  [BATCH * SEQ * INSZ];  // x in fp16
__device__ __align__(16) __half g_We  [G4 * KCAT];           // gate-interleaved [W_hh_e|W_ih_e]
__device__ __align__(16) __half g_Wd0 [G4 * HID];            // plain W_hh_d (gate-interleaved)
__device__ __align__(16) __half g_Wdf [G4 * HID];            // folded W_hh_d + W_ih_d@W_out
__device__ __align__(16) __half g_Wfc [HID * HID];
__device__ __align__(16) __half g_Wfcc[HID * HID];
__device__ __align__(16) __half g_Wout[OUTSZ * HID];
__device__ __align__(16) float  g_be  [G4];
__device__ __align__(16) float  g_bd0 [G4];
__device__ __align__(16) float  g_bdf [G4];

// ---------------------------------------------------------------------------
// Helpers
// ---------------------------------------------------------------------------
__device__ __forceinline__ void mma_f16(float* c, const uint32_t* a, const uint32_t* b) {
    asm volatile(
        "mma.sync.aligned.m16n8k16.row.col.f32.f16.f16.f32 "
        "{%0,%1,%2,%3}, {%4,%5,%6,%7}, {%8,%9}, {%0,%1,%2,%3};"
        : "+f"(c[0]), "+f"(c[1]), "+f"(c[2]), "+f"(c[3])
        : "r"(a[0]), "r"(a[1]), "r"(a[2]), "r"(a[3]), "r"(b[0]), "r"(b[1]));
}
__device__ __forceinline__ void ldsm4(uint32_t* r, uint32_t saddr) {
    asm volatile("ldmatrix.sync.aligned.m8n8.x4.shared.b16 {%0,%1,%2,%3}, [%4];"
        : "=r"(r[0]), "=r"(r[1]), "=r"(r[2]), "=r"(r[3]) : "r"(saddr));
}
__device__ __forceinline__ void cp16h(__half* smem, const __half* g) {
    uint32_t s = (uint32_t)__cvta_generic_to_shared(smem);
    asm volatile("cp.async.cg.shared.global [%0], [%1], 16;" :: "r"(s), "l"(g));
}
__device__ __forceinline__ uint32_t smem_u32(const void* p) {
    return (uint32_t)__cvta_generic_to_shared(p);
}
__device__ __forceinline__ float fsig(float x) {
    return __fdividef(1.0f, 1.0f + __expf(-x));
}
__device__ __forceinline__ float ftanh(float x) {
    return __fdividef(2.0f, 1.0f + __expf(-2.0f * x)) - 1.0f;
}

// ---------------------------------------------------------------------------
// Prep kernels
// ---------------------------------------------------------------------------
__global__ void prep_w(const float* __restrict__ Whh, const float* __restrict__ Wih,
                       const float* __restrict__ b1, const float* __restrict__ b2,
                       __half* __restrict__ Wcat, float* __restrict__ bcat)
{
    long idx = (long)blockIdx.x * blockDim.x + threadIdx.x;
    if (idx >= (long)G4 * KCAT) return;
    int row = (int)(idx / KCAT);
    int k   = (int)(idx % KCAT);
    int j = row >> 2, g = row & 3;
    int orow = g * HID + j;
    float w = (k < HID) ? Whh[(size_t)orow * HID + k]
                        : Wih[(size_t)orow * INSZ + (k - HID)];
    Wcat[idx] = __float2half_rn(w);
    if (k == 0) bcat[row] = b1[orow] + b2[orow];
}

// Decoder fold: Wd0 = Whh (interleaved), Wdf = Whh + Wih@Wout (interleaved),
// bd0 = b_ih+b_hh, bdf = bd0 + Wih@b_out. 16 rows per block.
__global__ void __launch_bounds__(256)
prep_wd(const float* __restrict__ Whh, const float* __restrict__ Wih,
        const float* __restrict__ Wout,
        const float* __restrict__ b1, const float* __restrict__ b2,
        const float* __restrict__ bo,
        __half* __restrict__ Wd0, __half* __restrict__ Wdf,
        float* __restrict__ bd0, float* __restrict__ bdf)
{
    __shared__ float wih_s[16][INSZ];
    __shared__ int orow_s[16];
    const int tid = threadIdx.x;
    const int rb = blockIdx.x * 16;
    if (tid < 16) {
        int row = rb + tid;
        orow_s[tid] = (row & 3) * HID + (row >> 2);
    }
    __syncthreads();
    for (int i = tid; i < 16 * INSZ; i += 256) {
        int r = i >> 7, o = i & 127;
        wih_s[r][o] = Wih[(size_t)orow_s[r] * INSZ + o];
    }
    __syncthreads();
    if (tid < 16) {
        float bf = 0.0f;
        for (int o = 0; o < INSZ; o++) bf += wih_s[tid][o] * bo[o];
        int orow = orow_s[tid];
        float bb = b1[orow] + b2[orow];
        bd0[rb + tid] = bb;
        bdf[rb + tid] = bb + bf;
    }
    for (int nc = 0; nc < 4; nc++) {
        int n = nc * 256 + tid;
        float acc[16], w0[16];
        #pragma unroll
        for (int r = 0; r < 16; r++) {
            w0[r] = Whh[(size_t)orow_s[r] * HID + n];
            acc[r] = w0[r];
        }
        for (int o = 0; o < INSZ; o++) {
            float w = Wout[(size_t)o * HID + n];
            #pragma unroll
            for (int r = 0; r < 16; r++) acc[r] += wih_s[r][o] * w;
        }
        #pragma unroll
        for (int r = 0; r < 16; r++) {
            Wd0[(size_t)(rb + r) * HID + n] = __float2half_rn(w0[r]);
            Wdf[(size_t)(rb + r) * HID + n] = __float2half_rn(acc[r]);
        }
    }
}

__global__ void f2h(const float* __restrict__ src, __half* __restrict__ dst, long n)
{
    long i = (long)blockIdx.x * blockDim.x + threadIdx.x;
    if (i < n) dst[i] = __float2half_rn(src[i]);
}

// ---------------------------------------------------------------------------
// Core GEMM (fp16 operands, fp32 accum), NS-stage cp.async pipeline, one
// __syncthreads per K-chunk, ldmatrix fragment loads. Warp tile 32x64.
// 128x128 CTA tile, 256 threads, 2 CTAs/SM (launch_bounds caps regs at 128)
// so two independent CTAs desynchronize barrier/pipeline stalls per SM.
// K chunks [cb, ce): chunk < HCH reads A1 (lda1); else A2 at k-1024 (lda2).
// MODE 0: LSTM epilogue (gate-interleaved cols; fp16 h -> O1, fp32 c -> O2)
// MODE 1: bias -> fp16 O1.  MODE 2: bias -> fp32 O1.
// MODE 4: bias -> fp32 scatter: row r -> out[(r&1023)*T*O + (r>>10)*O + col].
// ---------------------------------------------------------------------------
template<int TBM, int BN, int NS, int MODE>
__global__ void __launch_bounds__((TBM / 32) * (BN / 64) * 32, 2)
gemm_h(const __half* __restrict__ A1, int lda1,
       const __half* __restrict__ A2, int lda2,
       const __half* __restrict__ B,  int ldb,
       const float* __restrict__ bias,
       void* __restrict__ O1v, int ldo1,
       void* __restrict__ O2v, int ldo2,
       int cb, int ce, int first)
{
    constexpr int WM = TBM / 32;
    constexpr int WN = BN / 64;
    constexpr int NT = WM * WN * 32;
    constexpr int AS_ST = TBM * SMS_H;
    constexpr int BS_ST = BN * SMS_H;
    constexpr int IA = TBM * 8 / NT;
    constexpr int IB = BN * 8 / NT;

    extern __shared__ __half smh[];
    __half* As = smh;
    __half* Bs = smh + NS * AS_ST;

    const int tid  = threadIdx.x;
    const int lane = tid & 31;
    const int wid  = tid >> 5;
    const int wm   = wid % WM;
    const int wn   = wid / WM;
    const int lr   = lane >> 2;
    const int lc   = lane & 3;
    const int m0   = blockIdx.y * TBM;
    const int n0   = blockIdx.x * BN;

    const int a_row  = lane & 15;
    const int a_koff = (lane >> 4) << 3;
    const int b_row  = ((lane >> 4) << 3) + (lane & 7);
    const int b_koff = ((lane >> 3) & 1) << 3;

    float acc[2][8][4];
    #pragma unroll
    for (int mi = 0; mi < 2; mi++)
        #pragma unroll
        for (int nf = 0; nf < 8; nf++)
            #pragma unroll
            for (int t = 0; t < 4; t++) acc[mi][nf][t] = 0.0f;

    auto load_chunk = [&](int st, int chunk) {
        if (chunk < ce) {
            __half* as = As + st * AS_ST;
            __half* bs = Bs + st * BS_ST;
            const int k0 = chunk * CK;
            #pragma unroll
            for (int i = 0; i < IA; i++) {
                int q = tid + i * NT;
                int r = q >> 3, c8 = (q & 7) * 8;
                const __half* src = (chunk < HCH)
                    ? A1 + (size_t)(m0 + r) * lda1 + k0 + c8
                    : A2 + (size_t)(m0 + r) * lda2 + (k0 - HID) + c8;
                cp16h(as + r * SMS_H + c8, src);
            }
            #pragma unroll
            for (int i = 0; i < IB; i++) {
                int q = tid + i * NT;
                int r = q >> 3, c8 = (q & 7) * 8;
                cp16h(bs + r * SMS_H + c8, B + (size_t)(n0 + r) * ldb + k0 + c8);
            }
        }
        asm volatile("cp.async.commit_group;");
    };

    // Prologue: NS-1 chunks in flight
    #pragma unroll
    for (int s = 0; s < NS - 1; s++) load_chunk(s, cb + s);

    for (int ch = cb; ch < ce; ch++) {
        const int it = ch - cb;
        asm volatile("cp.async.wait_group %0;" :: "n"(NS - 2));
        __syncthreads();
        // Stage (it+NS-1)%NS == (it-1)%NS, consumed before the sync above.
        load_chunk((it + NS - 1) % NS, ch + NS - 1);

        const int st = it % NS;
        const uint32_t as_u = smem_u32(As + st * AS_ST + (wm * 32) * SMS_H);
        const uint32_t bs_u = smem_u32(Bs + st * BS_ST + (wn * 64) * SMS_H);
        #pragma unroll
        for (int ks = 0; ks < 4; ks++) {
            const int kk = ks * 16;
            uint32_t af[2][4];
            #pragma unroll
            for (int mi = 0; mi < 2; mi++)
                ldsm4(af[mi], as_u + (uint32_t)(((mi * 16 + a_row) * SMS_H + kk + a_koff) * 2));
            #pragma unroll
            for (int nfp = 0; nfp < 4; nfp++) {
                uint32_t bf4[4];
                ldsm4(bf4, bs_u + (uint32_t)(((nfp * 16 + b_row) * SMS_H + kk + b_koff) * 2));
                #pragma unroll
                for (int mi = 0; mi < 2; mi++) {
                    mma_f16(acc[mi][nfp * 2],     af[mi], &bf4[0]);
                    mma_f16(acc[mi][nfp * 2 + 1], af[mi], &bf4[2]);
                }
            }
        }
    }

    const int rb = m0 + wm * 32 + lr;
    if (MODE == 0) {
        __half* O1 = (__half*)O1v;
        float*  O2 = (float*)O2v;
        #pragma unroll
        for (int mi = 0; mi < 2; mi++) {
            #pragma unroll
            for (int nf = 0; nf < 8; nf++) {
                int cg = n0 + wn * 64 + nf * 8 + 2 * lc;   // = 4j+g (even)
                float v0 = acc[mi][nf][0] + bias[cg];
                float v1 = acc[mi][nf][1] + bias[cg + 1];
                float v2 = acc[mi][nf][2] + bias[cg];
                float v3 = acc[mi][nf][3] + bias[cg + 1];
                float p0 = __shfl_xor_sync(0xffffffffu, v0, 1);
                float p1 = __shfl_xor_sync(0xffffffffu, v1, 1);
                float p2 = __shfl_xor_sync(0xffffffffu, v2, 1);
                float p3 = __shfl_xor_sync(0xffffffffu, v3, 1);
                if ((lane & 1) == 0) {
                    int j  = cg >> 2;
                    int r0 = rb + mi * 16, r1 = r0 + 8;
                    {
                        float i_ = fsig(v0), f_ = fsig(v1);
                        float g_ = ftanh(p0), o_ = fsig(p1);
                        float co = first ? 0.0f : O2[(size_t)r0 * ldo2 + j];
                        float cn = f_ * co + i_ * g_;
                        O2[(size_t)r0 * ldo2 + j] = cn;
                        O1[(size_t)r0 * ldo1 + j] = __float2half_rn(o_ * ftanh(cn));
                    }
                    {
                        float i_ = fsig(v2), f_ = fsig(v3);
                        float g_ = ftanh(p2), o_ = fsig(p3);
                        float co = first ? 0.0f : O2[(size_t)r1 * ldo2 + j];
                        float cn = f_ * co + i_ * g_;
                        O2[(size_t)r1 * ldo2 + j] = cn;
                        O1[(size_t)r1 * ldo1 + j] = __float2half_rn(o_ * ftanh(cn));
                    }
                }
            }
        }
    } else {
        #pragma unroll
        for (int mi = 0; mi < 2; mi++) {
            #pragma unroll
            for (int nf = 0; nf < 8; nf++) {
                int cg = n0 + wn * 64 + nf * 8 + 2 * lc;
                float b0 = bias[cg], b1 = bias[cg + 1];
                int r0 = rb + mi * 16, r1 = r0 + 8;
                float u0 = acc[mi][nf][0] + b0, u1 = acc[mi][nf][1] + b1;
                float u2 = acc[mi][nf][2] + b0, u3 = acc[mi][nf][3] + b1;
                if (MODE == 1) {
                    __half* O1 = (__half*)O1v;
                    *(__half2*)&O1[(size_t)r0 * ldo1 + cg] = __floats2half2_rn(u0, u1);
                    *(__half2*)&O1[(size_t)r1 * ldo1 + cg] = __floats2half2_rn(u2, u3);
                } else if (MODE == 2) {
                    float* O1 = (float*)O1v;
                    *(float2*)&O1[(size_t)r0 * ldo1 + cg] = make_float2(u0, u1);
                    *(float2*)&O1[(size_t)r1 * ldo1 + cg] = make_float2(u2, u3);
                } else {   // MODE 4: scatter rows (b = r&1023, t = r>>10)
                    float* O1 = (float*)O1v;
                    size_t i0 = (size_t)(r0 & 1023) * (HORIZON * OUTSZ) + (size_t)(r0 >> 10) * OUTSZ + cg;
                    size_t i1 = (size_t)(r1 & 1023) * (HORIZON * OUTSZ) + (size_t)(r1 >> 10) * OUTSZ + cg;
                    *(float2*)&O1[i0] = make_float2(u0, u1);
                    *(float2*)&O1[i1] = make_float2(u2, u3);
                }
            }
        }
    }
}

// ---------------------------------------------------------------------------
// Launch sequence (graph-capturable: kernel launches only)
// ---------------------------------------------------------------------------
extern "C" void kernel_launch(void* const* d_in, const int* in_sizes, int n_in,
                              void* d_out, int out_size)
{
    const float* x      = (const float*)d_in[0];
    const float* W_ih_e = (const float*)d_in[1];
    const float* W_hh_e = (const float*)d_in[2];
    const float* b_ih_e = (const float*)d_in[3];
    const float* b_hh_e = (const float*)d_in[4];
    const float* W_ih_d = (const float*)d_in[5];
    const float* W_hh_d = (const float*)d_in[6];
    const float* b_ih_d = (const float*)d_in[7];
    const float* b_hh_d = (const float*)d_in[8];
    const float* W_fc   = (const float*)d_in[9];
    const float* b_fc   = (const float*)d_in[10];
    const float* W_fcc  = (const float*)d_in[11];
    const float* b_fcc  = (const float*)d_in[12];
    const float* W_out  = (const float*)d_in[13];
    const float* b_out  = (const float*)d_in[14];
    float* out = (float*)d_out;

    __half *h, *hall, *xh, *We, *Wd0, *Wdf, *Wfc, *Wfcc, *Wout;
    float *c, *cd, *be, *bd0, *bdf;
    cudaGetSymbolAddress((void**)&h,    g_h);
    cudaGetSymbolAddress((void**)&c,    g_c);
    cudaGetSymbolAddress((void**)&hall, g_hall);
    cudaGetSymbolAddress((void**)&cd,   g_cd);
    cudaGetSymbolAddress((void**)&xh,   g_xh);
    cudaGetSymbolAddress((void**)&We,   g_We);
    cudaGetSymbolAddress((void**)&Wd0,  g_Wd0);
    cudaGetSymbolAddress((void**)&Wdf,  g_Wdf);
    cudaGetSymbolAddress((void**)&Wfc,  g_Wfc);
    cudaGetSymbolAddress((void**)&Wfcc, g_Wfcc);
    cudaGetSymbolAddress((void**)&Wout, g_Wout);
    cudaGetSymbolAddress((void**)&be,   g_be);
    cudaGetSymbolAddress((void**)&bd0,  g_bd0);
    cudaGetSymbolAddress((void**)&bdf,  g_bdf);

    const int SMEM_S = 3 * (128 + 128) * SMS_H * 2;   // 110,592 B (2 CTAs/SM)
    cudaFuncSetAttribute((const void*)gemm_h<128, 128, 3, 0>,
                         cudaFuncAttributeMaxDynamicSharedMemorySize, SMEM_S);
    cudaFuncSetAttribute((const void*)gemm_h<128, 128, 3, 1>,
                         cudaFuncAttributeMaxDynamicSharedMemorySize, SMEM_S);
    cudaFuncSetAttribute((const void*)gemm_h<128, 128, 3, 2>,
                         cudaFuncAttributeMaxDynamicSharedMemorySize, SMEM_S);
    cudaFuncSetAttribute((const void*)gemm_h<128, 128, 3, 4>,
                         cudaFuncAttributeMaxDynamicSharedMemorySize, SMEM_S);

    // ---- prep ----
    {
        long total = (long)G4 * KCAT;
        int blocks = (int)((total + 255) / 256);
        prep_w<<<blocks, 256>>>(W_hh_e, W_ih_e, b_ih_e, b_hh_e, We, be);
        prep_wd<<<G4 / 16, 256>>>(W_hh_d, W_ih_d, W_out, b_ih_d, b_hh_d, b_out,
                                  Wd0, Wdf, bd0, bdf);
        long nx = (long)BATCH * SEQ * INSZ;
        f2h<<<(int)((nx + 255) / 256), 256>>>(x, xh, nx);
        long nw = (long)HID * HID;
        f2h<<<(int)((nw + 255) / 256), 256>>>(W_fc,  Wfc,  nw);
        f2h<<<(int)((nw + 255) / 256), 256>>>(W_fcc, Wfcc, nw);
        long no = (long)OUTSZ * HID;
        f2h<<<(int)((no + 255) / 256), 256>>>(W_out, Wout, no);
    }

    const size_t BH = (size_t)BATCH * HID;
    const dim3 gL(G4 / 128, BATCH / 128);       // (32, 8) = 256 CTAs, 2/SM
    const dim3 gB(HID / 128, BATCH / 128);      // (8, 8)
    const dim3 gF(1, (BATCH * HORIZON) / 128);  // (1, 192)

    // ---- encoder: 96 fused GEMM+LSTM steps ----
    int p = 0;
    for (int t = 0; t < SEQ; t++) {
        gemm_h<128, 128, 3, 0><<<gL, 256, SMEM_S>>>(
            h + (size_t)p * BH, HID,
            xh + (size_t)t * INSZ, SEQ * INSZ,
            We, KCAT, be,
            h + (size_t)(1 - p) * BH, HID,
            c, HID,
            (t == 0) ? HCH : 0, 18, (t == 0) ? 1 : 0);
        p ^= 1;
    }
    __half* h_fin = h + (size_t)p * BH;

    // ---- bridge: h_dec (fp16) -> hall slot 0; c_dec (fp32) -> cd ----
    gemm_h<128, 128, 3, 1><<<gB, 256, SMEM_S>>>(
        h_fin, HID, (const __half*)nullptr, 0, Wfc, HID, b_fc,
        hall, HID, nullptr, 0, 0, HCH, 0);
    gemm_h<128, 128, 3, 2><<<gB, 256, SMEM_S>>>(
        h_fin, HID, (const __half*)nullptr, 0, Wfcc, HID, b_fcc,
        cd, HID, nullptr, 0, 0, HCH, 0);

    // ---- decoder: 24 folded steps (out-proj folded into weights; K=1024) ----
    for (int t = 0; t < HORIZON; t++) {
        gemm_h<128, 128, 3, 0><<<gL, 256, SMEM_S>>>(
            hall + (size_t)t * BH, HID,
            (const __half*)nullptr, 0,
            (t == 0) ? Wd0 : Wdf, HID,
            (t == 0) ? bd0 : bdf,
            hall + (size_t)(t + 1) * BH, HID,
            cd, HID,
            0, HCH, 0);
    }

    // ---- batched output projection: out[b,t,:] = h_t[b] @ Wout^T + b_out ----
    gemm_h<128, 128, 3, 4><<<gF, 256, SMEM_S>>>(
        hall + BH, HID, (const __half*)nullptr, 0, Wout, HID, b_out,
        out, 0, nullptr, 0, 0, HCH, 0);
}